// round 7
// baseline (speedup 1.0000x reference)
#include <cuda_runtime.h>
#include <cstdint>

#define T_STEPS 16384
#define RING 8
#define FULLMASK 0xffffffffu

// Per-step blob, 36 floats per lane (32 lanes) = 1152 floats = 4608 B/step.
// Lane L (n = L&15, hi = L>=16, mhalf = hi ? 8..15 : 0..7):
//  f[0..7]   : A[n][m], m in mhalf                 (hg partial)
//  f[8..15]  : K1[m][n], m in mhalf                (r partial)
//  f[16..23] : K3[m][n], m in mhalf                (z partial)
//  f[24..31] : K5[m][n], m in mhalf                (hc partial)
//  f[32]     : u0[n] (lo) / u2[n] (hi)
//  f[33]     : bh[n]  (both halves)
//  f[34]     : u4[n]  (both halves)
//  f[35]     : pad
// Storage: blob[t][g][L] as float4, g = f>>2 (0..8), L = 0..31.
__device__ float g_blob[(size_t)T_STEPS * 1152];

#define BIDX(ln, f) ((((f) >> 2) * 128) + ((ln) * 4) + ((f) & 3))

__device__ __forceinline__ float tanha(float x){
    float y; asm("tanh.approx.f32 %0, %1;" : "=f"(y) : "f"(x)); return y;
}
__device__ __forceinline__ float sigm(float x){ return fmaf(0.5f, tanha(0.5f * x), 0.5f); }

// ---------------------------------------------------------------------------
// Precompute kernel: one warp per timestep.
// ---------------------------------------------------------------------------
__global__ void __launch_bounds__(128) precompute_kernel(
    const float* __restrict__ inputs, const float* __restrict__ a_list,
    const float* __restrict__ gcn_wx, const float* __restrict__ gcn_bx,
    const float* __restrict__ gcn_wh, const float* __restrict__ gcn_bh,
    const float* __restrict__ gru_k,  const float* __restrict__ gru_b)
{
    __shared__ float Lh[3][16][16];
    __shared__ float Lsum[16][16];
    __shared__ float dd[3][16], dis[3][16];
    __shared__ float Qh[4][256];
    __shared__ float bs[4][1152];
    __shared__ float xsc[4][80];

    int tid = threadIdx.x;

    if (tid < 48) {
        int l = tid / 16, j = tid % 16;
        float s = 0.0f;
        #pragma unroll
        for (int i = 0; i < 16; i++) s += a_list[l*256 + i*16 + j];
        dd[l][j] = s;
        dis[l][j] = rsqrtf(s);
    }
    __syncthreads();
    for (int e = tid; e < 768; e += 128) {
        int l = e / 256, rc = e % 256, i = rc / 16, j = rc % 16;
        float Lv = ((i == j) ? dd[l][i] : 0.0f) - a_list[e];
        Lh[l][i][j] = Lv * dis[l][i] * dis[l][j];
    }
    __syncthreads();
    {
        float* LsF = &Lsum[0][0];
        float* LhF = &Lh[0][0][0];
        for (int e = tid; e < 256; e += 128)
            LsF[e] = LhF[e] + LhF[256 + e] + LhF[512 + e];
    }
    __syncthreads();

    int w = tid >> 5, lane = tid & 31;
    int t = blockIdx.x * 4 + w;

    float* LsF = &Lsum[0][0];
    float* LhF = &Lh[0][0][0];

    // zero staging
    for (int i = lane; i < 1152; i += 32) bs[w][i] = 0.0f;
    __syncwarp();

    // ---- h-GCN matrix A ----
    const float* wh = gcn_wh + t * 13;
    float wh0 = wh[0], wh1 = wh[1], wh2 = wh[2];
    float wh10 = wh[10], wh11 = wh[11], wh12 = wh[12];

    for (int e = lane; e < 256; e += 32)
        Qh[w][e] = wh0*LhF[e] + wh1*LhF[256+e] + wh2*LhF[512+e];
    __syncwarp();

    float cA1 = wh0 * wh11, cA2 = wh0 * wh12;
    for (int e = lane; e < 256; e += 32) {
        int n = e >> 4, m = e & 15;
        float ql = 0.0f;
        #pragma unroll
        for (int k = 0; k < 16; k++) ql += Qh[w][n*16 + k] * LsF[k*16 + m];
        float Av = ((n == m) ? wh10 : 0.0f) + cA1 * LsF[e] + cA2 * ql;
        if (t == 0) Av = 0.0f;
        int ln = (m < 8) ? n : 16 + n;
        bs[w][BIDX(ln, m & 7)] = Av;
    }

    // ---- x-GCN -> xg ----
    const float* wx  = gcn_wx + t * 26;
    const float* xin = inputs + t * 32;
    {
        int c = lane >> 4, k = lane & 15;
        float s = 0.0f;
        #pragma unroll
        for (int m = 0; m < 16; m++) s += LsF[k*16 + m] * xin[m*2 + c];
        xsc[w][lane] = s;
    }
    __syncwarp();
    {
        int c = lane >> 4, n = lane & 15;
        float wc0 = wx[c*13], wc1 = wx[c*13 + 1], wc2 = wx[c*13 + 2];
        float g = 0.0f;
        #pragma unroll
        for (int k = 0; k < 16; k++)
            g += (wc0*Lh[0][n][k] + wc1*Lh[1][n][k] + wc2*Lh[2][n][k]) * xsc[w][c*16 + k];
        float part = wx[c*13 + 10] * xin[n*2 + c]
                   + wx[c*13 + 11] * wc0 * xsc[w][c*16 + n]
                   + wx[c*13 + 12] * wc0 * g;
        xsc[w][32 + lane] = part;
    }
    __syncwarp();
    if (lane < 16) {
        float xg = xsc[w][32 + lane] + xsc[w][48 + lane] + gcn_bx[t*16 + lane];
        xsc[w][64 + lane] = fmaxf(xg, 0.0f);
    }
    __syncwarp();

    // ---- u vectors ----
    const float* gk = gru_k + (size_t)t * 1536;
    const float* gb = gru_b + t * 96;
    for (int e = lane; e < 48; e += 32) {
        int i2 = e >> 4, j = e & 15;
        const float* Kb = gk + i2 * 512;
        float u = gb[i2*32 + j] + gb[i2*32 + 16 + j];
        #pragma unroll
        for (int m = 0; m < 16; m++) u += xsc[w][64 + m] * Kb[m*16 + j];
        if (i2 == 0)      bs[w][BIDX(j, 32)] = u;
        else if (i2 == 1) bs[w][BIDX(16 + j, 32)] = u;
        else { bs[w][BIDX(j, 34)] = u; bs[w][BIDX(16 + j, 34)] = u; }
    }

    // ---- K1/K3/K5 half-columns: f = 8 + which*8 + (m&7), lane by m-half ----
    for (int e = lane; e < 768; e += 32) {
        int which = e >> 8, rc = e & 255, m = rc >> 4, nn = rc & 15;
        float kv = gk[(2*which + 1)*256 + m*16 + nn];
        int ln = (m < 8) ? nn : 16 + nn;
        int f  = 8 + which*8 + (m & 7);
        bs[w][BIDX(ln, f)] = kv;
    }

    // ---- bh (both halves) ----
    if (lane < 16) {
        float bh = (t == 0) ? 0.0f : gcn_bh[t*16 + lane];
        bs[w][BIDX(lane, 33)] = bh;
        bs[w][BIDX(16 + lane, 33)] = bh;
    }
    __syncwarp();

    float4* dst = reinterpret_cast<float4*>(g_blob + (size_t)t * 1152);
    const float4* srcv = reinterpret_cast<const float4*>(bs[w]);
    for (int i = lane; i < 288; i += 32) dst[i] = srcv[i];
}

// ---------------------------------------------------------------------------
// Recurrence kernel
// ---------------------------------------------------------------------------
__device__ __forceinline__ int ldacq(uint32_t a){
    int v; asm volatile("ld.acquire.cta.shared::cta.b32 %0, [%1];" : "=r"(v) : "r"(a)); return v;
}

// Predicated global store: no BSSY/BSYNC.
__device__ __forceinline__ void st_pred(float* p, float v, uint32_t pred){
    asm volatile("{\n\t.reg .pred q;\n\tsetp.ne.u32 q, %2, 0;\n\t@q st.global.f32 [%0], %1;\n\t}"
                 :: "l"(p), "f"(v), "r"(pred) : "memory");
}

__device__ __forceinline__ void gru_step(const float (&w)[36], float (&hv)[8],
                                         float* __restrict__ out, int t,
                                         uint32_t hip, int rsrc, int hsrc)
{
    // hg = relu(A@h + bh), split across halves
    float a0 = w[0]*hv[0];
    float a1 = w[1]*hv[1];
    a0 = fmaf(w[2], hv[2], a0); a1 = fmaf(w[3], hv[3], a1);
    a0 = fmaf(w[4], hv[4], a0); a1 = fmaf(w[5], hv[5], a1);
    a0 = fmaf(w[6], hv[6], a0); a1 = fmaf(w[7], hv[7], a1);
    float pa = a0 + a1;
    pa += __shfl_xor_sync(FULLMASK, pa, 16);
    float hg = fmaxf(pa + w[33], 0.0f);

    // broadcast own-half hg (8 values)
    float hgv[8];
    #pragma unroll
    for (int j = 0; j < 8; j++) hgv[j] = __shfl_sync(FULLMASK, hg, rsrc + j);

    // r and z partials over own m-half (4 chains)
    float rp0 = hgv[0]*w[8],  rp1 = hgv[1]*w[9];
    float zp0 = hgv[0]*w[16], zp1 = hgv[1]*w[17];
    rp0 = fmaf(hgv[2], w[10], rp0); rp1 = fmaf(hgv[3], w[11], rp1);
    zp0 = fmaf(hgv[2], w[18], zp0); zp1 = fmaf(hgv[3], w[19], zp1);
    rp0 = fmaf(hgv[4], w[12], rp0); rp1 = fmaf(hgv[5], w[13], rp1);
    zp0 = fmaf(hgv[4], w[20], zp0); zp1 = fmaf(hgv[5], w[21], zp1);
    rp0 = fmaf(hgv[6], w[14], rp0); rp1 = fmaf(hgv[7], w[15], rp1);
    zp0 = fmaf(hgv[6], w[22], zp0); zp1 = fmaf(hgv[7], w[23], zp1);
    float rp = rp0 + rp1, zp = zp0 + zp1;

    // single cross-half exchange: lo sends zp (hi needs it), hi sends rp (lo needs it)
    float send = hip ? rp : zp;
    float got  = __shfl_xor_sync(FULLMASK, send, 16);
    float keep = hip ? zp : rp;
    float s = sigm(w[32] + keep + got);   // lo: r, hi: z
    float rh = s * hg;                    // meaningful in lo lanes (r*hg)

    // broadcast rh (own m-half: rh[m] lives in lo lane m)
    float rhv[8];
    #pragma unroll
    for (int j = 0; j < 8; j++) rhv[j] = __shfl_sync(FULLMASK, rh, rsrc + j);

    // hc partial, split across halves
    float p0 = rhv[0]*w[24], p1 = rhv[1]*w[25];
    p0 = fmaf(rhv[2], w[26], p0); p1 = fmaf(rhv[3], w[27], p1);
    p0 = fmaf(rhv[4], w[28], p0); p1 = fmaf(rhv[5], w[29], p1);
    p0 = fmaf(rhv[6], w[30], p0); p1 = fmaf(rhv[7], w[31], p1);
    float p = p0 + p1;
    p += __shfl_xor_sync(FULLMASK, p, 16);
    float hc = tanha(p + w[34]);
    float hn = fmaf(s, hg - hc, hc);      // meaningful in hi lanes (s = z)

    // broadcast next h (own m-half, sourced from hi lanes)
    #pragma unroll
    for (int j = 0; j < 8; j++) hv[j] = __shfl_sync(FULLMASK, hn, hsrc + j);

    // predicated store, off the critical chain
    st_pred(out + t * 16 + (threadIdx.x & 15), hn, hip);
}

#define LOADW(dst, slot)                                                     \
    {                                                                        \
        const float4* _s = &ring[(slot) * 288 + lane];                       \
        float4* _d = reinterpret_cast<float4*>(dst);                         \
        _Pragma("unroll")                                                    \
        for (int _j = 0; _j < 9; _j++) _d[_j] = _s[_j * 32];                 \
    }

__global__ void __launch_bounds__(128) recurrent_kernel(float* __restrict__ out)
{
    __shared__ float4 ring[RING * 288];
    __shared__ int Wsh;
    __shared__ int cons_prog;

    int tid = threadIdx.x;
    if (tid == 0) { Wsh = 0; cons_prog = 0; }
    __syncthreads();

    int w = tid >> 5, lane = tid & 31;

    if (w == 0) {
        // ---------------- consumer ----------------
        uint32_t hip = (lane >= 16) ? 1u : 0u;
        int rsrc = (lane >= 16) ? 8 : 0;
        int hsrc = (lane >= 16) ? 24 : 16;

        float hv[8];
        #pragma unroll
        for (int j = 0; j < 8; j++) hv[j] = 0.0f;

        uint32_t Wa = (uint32_t)__cvta_generic_to_shared(&Wsh);
        int Wloc = 0;

        float wa[36], wb[36];
        while (Wloc < 1) Wloc = ldacq(Wa);
        LOADW(wa, 0);

        #pragma unroll 1
        for (int t = 0; t < T_STEPS; t += 2) {
            // single poll covers both prefetches (t+1 needs >=t+2, t+2 needs >=t+3)
            while (Wloc < t + 3) Wloc = ldacq(Wa);

            LOADW(wb, (t + 1) & (RING - 1));
            gru_step(wa, hv, out, t, hip, rsrc, hsrc);

            LOADW(wa, (t + 2) & (RING - 1));   // stale data on final iter: unused
            gru_step(wb, hv, out, t + 1, hip, rsrc, hsrc);

            // all lanes store same value to same address: no divergence
            *(volatile int*)&cons_prog = t + 2;
        }
    } else if (w == 1) {
        // ---------------- producer (single warp, monotonic watermark) ----
        // wait_group 2 lag: publish t-1 after commit t. Slack vs consumer = 3.
        uint32_t ringb = (uint32_t)__cvta_generic_to_shared(ring);
        uint32_t Wa = (uint32_t)__cvta_generic_to_shared(&Wsh);
        const float4* blob4 = reinterpret_cast<const float4*>(g_blob);

        for (int t = 0; t < T_STEPS; t++) {
            if (t >= RING) {
                while (*(volatile int*)&cons_prog < t - RING + 1) __nanosleep(32);
            }
            const float4* src = blob4 + (size_t)t * 288 + lane;
            uint32_t dst = ringb + ((uint32_t)(t & (RING - 1)) * 288 + lane) * 16;
            #pragma unroll
            for (int j = 0; j < 9; j++) {
                asm volatile("cp.async.cg.shared.global [%0], [%1], 16;"
                             :: "r"(dst + j * 512), "l"(src + j * 32) : "memory");
            }
            asm volatile("cp.async.commit_group;" ::: "memory");
            asm volatile("cp.async.wait_group 2;" ::: "memory");
            __threadfence_block();
            __syncwarp();
            if (lane == 0 && t >= 2) {
                asm volatile("st.release.cta.shared::cta.b32 [%0], %1;"
                             :: "r"(Wa), "r"(t - 1) : "memory");
            }
        }
        asm volatile("cp.async.wait_group 0;" ::: "memory");
        __threadfence_block();
        __syncwarp();
        if (lane == 0) {
            // over-publish so the consumer's final hoisted poll (t+3 up to
            // T_STEPS+1) is satisfiable; the extra slots are never consumed.
            asm volatile("st.release.cta.shared::cta.b32 [%0], %1;"
                         :: "r"(Wa), "r"(T_STEPS + RING) : "memory");
        }
    } else if (w == 2) {
        // ---------------- L2 prefetcher ----------------
        const char* p = reinterpret_cast<const char*>(g_blob);
        size_t total = (size_t)T_STEPS * 4608;
        #pragma unroll 4
        for (size_t off = (size_t)lane * 128; off < total; off += 4096) {
            asm volatile("prefetch.global.L2 [%0];" :: "l"(p + off));
        }
    }
}

extern "C" void kernel_launch(void* const* d_in, const int* in_sizes, int n_in,
                              void* d_out, int out_size)
{
    const float* inputs = (const float*)d_in[0];
    const float* a_list = (const float*)d_in[1];
    const float* gcn_wx = (const float*)d_in[2];
    const float* gcn_bx = (const float*)d_in[3];
    const float* gcn_wh = (const float*)d_in[4];
    const float* gcn_bh = (const float*)d_in[5];
    const float* gru_k  = (const float*)d_in[6];
    const float* gru_b  = (const float*)d_in[7];

    precompute_kernel<<<4096, 128>>>(inputs, a_list, gcn_wx, gcn_bx,
                                     gcn_wh, gcn_bh, gru_k, gru_b);
    recurrent_kernel<<<1, 128>>>((float*)d_out);
}

// round 8
// speedup vs baseline: 1.0673x; 1.0673x over previous
#include <cuda_runtime.h>
#include <cstdint>

#define T_STEPS 16384
#define RING 8
#define FULLMASK 0xffffffffu

// Per-step blob, 36 floats per lane (32 lanes) = 1152 floats = 4608 B/step.
// Lane L (n = L&15, hi = L>=16):
//  f[0..7]   : A[n][m] for m in lo?0..7:8..15      (hg partial)
//  f[8..23]  : K1 col n (lo) / K3 col n (hi)       (r/z dot)
//  f[24..31] : K5[m][n], m in lo?0..7:8..15        (hc partial)
//  f[32]     : u0[n] (lo) / u2[n] (hi)
//  f[33]     : bh[n]  (both halves)
//  f[34]     : u4[n]  (both halves)
//  f[35]     : pad
// Storage: blob[t][g][L] as float4, g = f>>2 (0..8), L = 0..31.
__device__ float g_blob[(size_t)T_STEPS * 1152];

#define BIDX(ln, f) ((((f) >> 2) * 128) + ((ln) * 4) + ((f) & 3))

__device__ __forceinline__ float tanha(float x){
    float y; asm("tanh.approx.f32 %0, %1;" : "=f"(y) : "f"(x)); return y;
}
__device__ __forceinline__ float sigm(float x){ return fmaf(0.5f, tanha(0.5f * x), 0.5f); }

// ---------------------------------------------------------------------------
// Precompute kernel: one warp per timestep.
// ---------------------------------------------------------------------------
__global__ void __launch_bounds__(128) precompute_kernel(
    const float* __restrict__ inputs, const float* __restrict__ a_list,
    const float* __restrict__ gcn_wx, const float* __restrict__ gcn_bx,
    const float* __restrict__ gcn_wh, const float* __restrict__ gcn_bh,
    const float* __restrict__ gru_k,  const float* __restrict__ gru_b)
{
    __shared__ float Lh[3][16][16];
    __shared__ float Lsum[16][16];
    __shared__ float dd[3][16], dis[3][16];
    __shared__ float Qh[4][256];
    __shared__ float bs[4][1152];
    __shared__ float xsc[4][80];

    int tid = threadIdx.x;

    if (tid < 48) {
        int l = tid / 16, j = tid % 16;
        float s = 0.0f;
        #pragma unroll
        for (int i = 0; i < 16; i++) s += a_list[l*256 + i*16 + j];
        dd[l][j] = s;
        dis[l][j] = rsqrtf(s);
    }
    __syncthreads();
    for (int e = tid; e < 768; e += 128) {
        int l = e / 256, rc = e % 256, i = rc / 16, j = rc % 16;
        float Lv = ((i == j) ? dd[l][i] : 0.0f) - a_list[e];
        Lh[l][i][j] = Lv * dis[l][i] * dis[l][j];
    }
    __syncthreads();
    {
        float* LsF = &Lsum[0][0];
        float* LhF = &Lh[0][0][0];
        for (int e = tid; e < 256; e += 128)
            LsF[e] = LhF[e] + LhF[256 + e] + LhF[512 + e];
    }
    __syncthreads();

    int w = tid >> 5, lane = tid & 31;
    int t = blockIdx.x * 4 + w;

    float* LsF = &Lsum[0][0];
    float* LhF = &Lh[0][0][0];

    // zero staging
    for (int i = lane; i < 1152; i += 32) bs[w][i] = 0.0f;
    __syncwarp();

    // ---- h-GCN matrix A ----
    const float* wh = gcn_wh + t * 13;
    float wh0 = wh[0], wh1 = wh[1], wh2 = wh[2];
    float wh10 = wh[10], wh11 = wh[11], wh12 = wh[12];

    for (int e = lane; e < 256; e += 32)
        Qh[w][e] = wh0*LhF[e] + wh1*LhF[256+e] + wh2*LhF[512+e];
    __syncwarp();

    float cA1 = wh0 * wh11, cA2 = wh0 * wh12;
    for (int e = lane; e < 256; e += 32) {
        int n = e >> 4, m = e & 15;
        float ql = 0.0f;
        #pragma unroll
        for (int k = 0; k < 16; k++) ql += Qh[w][n*16 + k] * LsF[k*16 + m];
        float Av = ((n == m) ? wh10 : 0.0f) + cA1 * LsF[e] + cA2 * ql;
        if (t == 0) Av = 0.0f;
        int ln = (m < 8) ? n : 16 + n;
        bs[w][BIDX(ln, m & 7)] = Av;
    }

    // ---- x-GCN -> xg ----
    const float* wx  = gcn_wx + t * 26;
    const float* xin = inputs + t * 32;
    {
        int c = lane >> 4, k = lane & 15;
        float s = 0.0f;
        #pragma unroll
        for (int m = 0; m < 16; m++) s += LsF[k*16 + m] * xin[m*2 + c];
        xsc[w][lane] = s;
    }
    __syncwarp();
    {
        int c = lane >> 4, n = lane & 15;
        float wc0 = wx[c*13], wc1 = wx[c*13 + 1], wc2 = wx[c*13 + 2];
        float g = 0.0f;
        #pragma unroll
        for (int k = 0; k < 16; k++)
            g += (wc0*Lh[0][n][k] + wc1*Lh[1][n][k] + wc2*Lh[2][n][k]) * xsc[w][c*16 + k];
        float part = wx[c*13 + 10] * xin[n*2 + c]
                   + wx[c*13 + 11] * wc0 * xsc[w][c*16 + n]
                   + wx[c*13 + 12] * wc0 * g;
        xsc[w][32 + lane] = part;
    }
    __syncwarp();
    if (lane < 16) {
        float xg = xsc[w][32 + lane] + xsc[w][48 + lane] + gcn_bx[t*16 + lane];
        xsc[w][64 + lane] = fmaxf(xg, 0.0f);
    }
    __syncwarp();

    // ---- u vectors ----
    const float* gk = gru_k + (size_t)t * 1536;
    const float* gb = gru_b + t * 96;
    for (int e = lane; e < 48; e += 32) {
        int i2 = e >> 4, j = e & 15;
        const float* Kb = gk + i2 * 512;
        float u = gb[i2*32 + j] + gb[i2*32 + 16 + j];
        #pragma unroll
        for (int m = 0; m < 16; m++) u += xsc[w][64 + m] * Kb[m*16 + j];
        if (i2 == 0)      bs[w][BIDX(j, 32)] = u;
        else if (i2 == 1) bs[w][BIDX(16 + j, 32)] = u;
        else { bs[w][BIDX(j, 34)] = u; bs[w][BIDX(16 + j, 34)] = u; }
    }

    // ---- K1/K3/K5 columns (R6 layout) ----
    for (int e = lane; e < 768; e += 32) {
        int which = e >> 8, rc = e & 255, m = rc >> 4, nn = rc & 15;
        float kv = gk[(2*which + 1)*256 + m*16 + nn];
        int ln, f;
        if (which == 0)      { ln = nn;                        f = 8 + m; }
        else if (which == 1) { ln = 16 + nn;                   f = 8 + m; }
        else                 { ln = (m < 8) ? nn : 16 + nn;    f = 24 + (m & 7); }
        bs[w][BIDX(ln, f)] = kv;
    }

    // ---- bh (both halves) ----
    if (lane < 16) {
        float bh = (t == 0) ? 0.0f : gcn_bh[t*16 + lane];
        bs[w][BIDX(lane, 33)] = bh;
        bs[w][BIDX(16 + lane, 33)] = bh;
    }
    __syncwarp();

    float4* dst = reinterpret_cast<float4*>(g_blob + (size_t)t * 1152);
    const float4* srcv = reinterpret_cast<const float4*>(bs[w]);
    for (int i = lane; i < 288; i += 32) dst[i] = srcv[i];
}

// ---------------------------------------------------------------------------
// Recurrence kernel
// ---------------------------------------------------------------------------
__device__ __forceinline__ int ldacq(uint32_t a){
    int v; asm volatile("ld.acquire.cta.shared::cta.b32 %0, [%1];" : "=r"(v) : "r"(a)); return v;
}

// Predicated global store: no BSSY/BSYNC.
__device__ __forceinline__ void st_pred(float* p, float v, uint32_t pred){
    asm volatile("{\n\t.reg .pred q;\n\tsetp.ne.u32 q, %2, 0;\n\t@q st.global.f32 [%0], %1;\n\t}"
                 :: "l"(p), "f"(v), "r"(pred) : "memory");
}

__device__ __forceinline__ void gru_step(const float (&w)[36], float (&hv)[8],
                                         float* __restrict__ out, int t,
                                         uint32_t hip, int rsrc, int hsrc)
{
    // hg = relu(A@h + bh), split across halves; 4 accumulator chains
    float a0 = w[0]*hv[0], a1 = w[1]*hv[1], a2 = w[2]*hv[2], a3 = w[3]*hv[3];
    a0 = fmaf(w[4], hv[4], a0); a1 = fmaf(w[5], hv[5], a1);
    a2 = fmaf(w[6], hv[6], a2); a3 = fmaf(w[7], hv[7], a3);
    float pa = (a0 + a1) + (a2 + a3);
    pa += __shfl_xor_sync(FULLMASK, pa, 16);
    float hg = fmaxf(pa + w[33], 0.0f);

    // broadcast hg (16 values, all independent SHFLs - they pipeline)
    float hgv[16];
    #pragma unroll
    for (int m = 0; m < 16; m++) hgv[m] = __shfl_sync(FULLMASK, hg, m);

    // r (lo) / z (hi) dot: 4 accumulator chains
    float v0 = fmaf(hgv[0], w[8],  w[32]);
    float v1 = hgv[1]*w[9];
    float v2 = hgv[2]*w[10];
    float v3 = hgv[3]*w[11];
    #pragma unroll
    for (int m = 4; m < 16; m += 4) {
        v0 = fmaf(hgv[m],   w[8 + m],  v0);
        v1 = fmaf(hgv[m+1], w[9 + m],  v1);
        v2 = fmaf(hgv[m+2], w[10 + m], v2);
        v3 = fmaf(hgv[m+3], w[11 + m], v3);
    }
    float s = sigm((v0 + v1) + (v2 + v3));
    float rh = s * hg;     // meaningful in lo lanes (r*hg)

    // broadcast rh (own m-half: 8 values from lo lanes)
    float rhv[8];
    #pragma unroll
    for (int j = 0; j < 8; j++) rhv[j] = __shfl_sync(FULLMASK, rh, rsrc + j);

    // hc partial, split across halves; 4 chains
    float p0 = rhv[0]*w[24], p1 = rhv[1]*w[25], p2 = rhv[2]*w[26], p3 = rhv[3]*w[27];
    p0 = fmaf(rhv[4], w[28], p0); p1 = fmaf(rhv[5], w[29], p1);
    p2 = fmaf(rhv[6], w[30], p2); p3 = fmaf(rhv[7], w[31], p3);
    float p = (p0 + p1) + (p2 + p3);
    p += __shfl_xor_sync(FULLMASK, p, 16);
    float hc = tanha(p + w[34]);
    float hn = fmaf(s, hg - hc, hc);      // meaningful in hi lanes (s = z)

    // broadcast next h (own m-half, sourced from hi lanes)
    #pragma unroll
    for (int j = 0; j < 8; j++) hv[j] = __shfl_sync(FULLMASK, hn, hsrc + j);

    // predicated store, off the critical chain
    st_pred(out + t * 16 + (threadIdx.x & 15), hn, hip);
}

#define LOADW(dst, slot)                                                     \
    {                                                                        \
        const float4* _s = &ring[(slot) * 288 + lane];                       \
        float4* _d = reinterpret_cast<float4*>(dst);                         \
        _Pragma("unroll")                                                    \
        for (int _j = 0; _j < 9; _j++) _d[_j] = _s[_j * 32];                 \
    }

__global__ void __launch_bounds__(128) recurrent_kernel(float* __restrict__ out)
{
    __shared__ float4 ring[RING * 288];
    __shared__ int Wsh;
    __shared__ int cons_prog;

    int tid = threadIdx.x;
    if (tid == 0) { Wsh = 0; cons_prog = 0; }
    __syncthreads();

    int w = tid >> 5, lane = tid & 31;

    if (w == 0) {
        // ---------------- consumer ----------------
        uint32_t hip = (lane >= 16) ? 1u : 0u;
        int rsrc = (lane >= 16) ? 8 : 0;
        int hsrc = (lane >= 16) ? 24 : 16;

        float hv[8];
        #pragma unroll
        for (int j = 0; j < 8; j++) hv[j] = 0.0f;

        uint32_t Wa = (uint32_t)__cvta_generic_to_shared(&Wsh);
        int Wloc = 0;

        float wa[36], wb[36];
        while (Wloc < 1) Wloc = ldacq(Wa);
        LOADW(wa, 0);

        #pragma unroll 1
        for (int t = 0; t < T_STEPS; t += 2) {
            // single poll covers both prefetches (t+1 needs >=t+2, t+2 needs >=t+3)
            while (Wloc < t + 3) Wloc = ldacq(Wa);

            LOADW(wb, (t + 1) & (RING - 1));
            gru_step(wa, hv, out, t, hip, rsrc, hsrc);

            LOADW(wa, (t + 2) & (RING - 1));   // stale data on final iter: unused
            gru_step(wb, hv, out, t + 1, hip, rsrc, hsrc);

            // all lanes store same value to same address: no divergence
            *(volatile int*)&cons_prog = t + 2;
        }
    } else if (w == 1) {
        // ---------------- producer (single warp, monotonic watermark) ----
        // wait_group 2 lag: publish t-1 after commit t. Slack vs consumer = 3.
        uint32_t ringb = (uint32_t)__cvta_generic_to_shared(ring);
        uint32_t Wa = (uint32_t)__cvta_generic_to_shared(&Wsh);
        const float4* blob4 = reinterpret_cast<const float4*>(g_blob);

        for (int t = 0; t < T_STEPS; t++) {
            if (t >= RING) {
                while (*(volatile int*)&cons_prog < t - RING + 1) __nanosleep(32);
            }
            const float4* src = blob4 + (size_t)t * 288 + lane;
            uint32_t dst = ringb + ((uint32_t)(t & (RING - 1)) * 288 + lane) * 16;
            #pragma unroll
            for (int j = 0; j < 9; j++) {
                asm volatile("cp.async.cg.shared.global [%0], [%1], 16;"
                             :: "r"(dst + j * 512), "l"(src + j * 32) : "memory");
            }
            asm volatile("cp.async.commit_group;" ::: "memory");
            asm volatile("cp.async.wait_group 2;" ::: "memory");
            __threadfence_block();
            __syncwarp();
            if (lane == 0 && t >= 2) {
                asm volatile("st.release.cta.shared::cta.b32 [%0], %1;"
                             :: "r"(Wa), "r"(t - 1) : "memory");
            }
        }
        asm volatile("cp.async.wait_group 0;" ::: "memory");
        __threadfence_block();
        __syncwarp();
        if (lane == 0) {
            // over-publish so the consumer's final hoisted poll (up to T+1)
            // is satisfiable; the extra slots are never consumed.
            asm volatile("st.release.cta.shared::cta.b32 [%0], %1;"
                         :: "r"(Wa), "r"(T_STEPS + RING) : "memory");
        }
    } else if (w == 2) {
        // ---------------- L2 prefetcher ----------------
        const char* p = reinterpret_cast<const char*>(g_blob);
        size_t total = (size_t)T_STEPS * 4608;
        #pragma unroll 4
        for (size_t off = (size_t)lane * 128; off < total; off += 4096) {
            asm volatile("prefetch.global.L2 [%0];" :: "l"(p + off));
        }
    }
}

extern "C" void kernel_launch(void* const* d_in, const int* in_sizes, int n_in,
                              void* d_out, int out_size)
{
    const float* inputs = (const float*)d_in[0];
    const float* a_list = (const float*)d_in[1];
    const float* gcn_wx = (const float*)d_in[2];
    const float* gcn_bx = (const float*)d_in[3];
    const float* gcn_wh = (const float*)d_in[4];
    const float* gcn_bh = (const float*)d_in[5];
    const float* gru_k  = (const float*)d_in[6];
    const float* gru_b  = (const float*)d_in[7];

    precompute_kernel<<<4096, 128>>>(inputs, a_list, gcn_wx, gcn_bx,
                                     gcn_wh, gcn_bh, gru_k, gru_b);
    recurrent_kernel<<<1, 128>>>((float*)d_out);
}

// round 9
// speedup vs baseline: 1.2427x; 1.1644x over previous
#include <cuda_runtime.h>
#include <cstdint>

#define T_STEPS 16384
#define RING 8
#define FULLMASK 0xffffffffu

// Per-step blob, 36 floats per lane (32 lanes) = 1152 floats = 4608 B/step.
// Lane L (n = L&15, hi = L>=16):
//  f[0..7]   : A[n][m] for m in lo?0..7:8..15      (hg partial)
//  f[8..23]  : K1 col n (lo) / K3 col n (hi)       (r/z dot)
//  f[24..31] : K5[m][n], m in lo?0..7:8..15        (hc partial)
//  f[32]     : u0[n] (lo) / u2[n] (hi)
//  f[33]     : bh[n]/2  (both halves; halves sum across the xor)
//  f[34]     : u4[n]/2  (both halves)
//  f[35]     : pad
// Storage: blob[t][g][L] as float4, g = f>>2 (0..8), L = 0..31.
__device__ float g_blob[(size_t)T_STEPS * 1152];

#define BIDX(ln, f) ((((f) >> 2) * 128) + ((ln) * 4) + ((f) & 3))

__device__ __forceinline__ float tanha(float x){
    float y; asm("tanh.approx.f32 %0, %1;" : "=f"(y) : "f"(x)); return y;
}
__device__ __forceinline__ float sigm(float x){ return fmaf(0.5f, tanha(0.5f * x), 0.5f); }

// ---------------------------------------------------------------------------
// Precompute kernel: one warp per timestep.
// ---------------------------------------------------------------------------
__global__ void __launch_bounds__(128) precompute_kernel(
    const float* __restrict__ inputs, const float* __restrict__ a_list,
    const float* __restrict__ gcn_wx, const float* __restrict__ gcn_bx,
    const float* __restrict__ gcn_wh, const float* __restrict__ gcn_bh,
    const float* __restrict__ gru_k,  const float* __restrict__ gru_b)
{
    __shared__ float Lh[3][16][16];
    __shared__ float Lsum[16][16];
    __shared__ float dd[3][16], dis[3][16];
    __shared__ float Qh[4][256];
    __shared__ float bs[4][1152];
    __shared__ float xsc[4][80];

    int tid = threadIdx.x;

    if (tid < 48) {
        int l = tid / 16, j = tid % 16;
        float s = 0.0f;
        #pragma unroll
        for (int i = 0; i < 16; i++) s += a_list[l*256 + i*16 + j];
        dd[l][j] = s;
        dis[l][j] = rsqrtf(s);
    }
    __syncthreads();
    for (int e = tid; e < 768; e += 128) {
        int l = e / 256, rc = e % 256, i = rc / 16, j = rc % 16;
        float Lv = ((i == j) ? dd[l][i] : 0.0f) - a_list[e];
        Lh[l][i][j] = Lv * dis[l][i] * dis[l][j];
    }
    __syncthreads();
    {
        float* LsF = &Lsum[0][0];
        float* LhF = &Lh[0][0][0];
        for (int e = tid; e < 256; e += 128)
            LsF[e] = LhF[e] + LhF[256 + e] + LhF[512 + e];
    }
    __syncthreads();

    int w = tid >> 5, lane = tid & 31;
    int t = blockIdx.x * 4 + w;

    float* LsF = &Lsum[0][0];
    float* LhF = &Lh[0][0][0];

    // zero staging
    for (int i = lane; i < 1152; i += 32) bs[w][i] = 0.0f;
    __syncwarp();

    // ---- h-GCN matrix A ----
    const float* wh = gcn_wh + t * 13;
    float wh0 = wh[0], wh1 = wh[1], wh2 = wh[2];
    float wh10 = wh[10], wh11 = wh[11], wh12 = wh[12];

    for (int e = lane; e < 256; e += 32)
        Qh[w][e] = wh0*LhF[e] + wh1*LhF[256+e] + wh2*LhF[512+e];
    __syncwarp();

    float cA1 = wh0 * wh11, cA2 = wh0 * wh12;
    for (int e = lane; e < 256; e += 32) {
        int n = e >> 4, m = e & 15;
        float ql = 0.0f;
        #pragma unroll
        for (int k = 0; k < 16; k++) ql += Qh[w][n*16 + k] * LsF[k*16 + m];
        float Av = ((n == m) ? wh10 : 0.0f) + cA1 * LsF[e] + cA2 * ql;
        if (t == 0) Av = 0.0f;
        int ln = (m < 8) ? n : 16 + n;
        bs[w][BIDX(ln, m & 7)] = Av;
    }

    // ---- x-GCN -> xg ----
    const float* wx  = gcn_wx + t * 26;
    const float* xin = inputs + t * 32;
    {
        int c = lane >> 4, k = lane & 15;
        float s = 0.0f;
        #pragma unroll
        for (int m = 0; m < 16; m++) s += LsF[k*16 + m] * xin[m*2 + c];
        xsc[w][lane] = s;
    }
    __syncwarp();
    {
        int c = lane >> 4, n = lane & 15;
        float wc0 = wx[c*13], wc1 = wx[c*13 + 1], wc2 = wx[c*13 + 2];
        float g = 0.0f;
        #pragma unroll
        for (int k = 0; k < 16; k++)
            g += (wc0*Lh[0][n][k] + wc1*Lh[1][n][k] + wc2*Lh[2][n][k]) * xsc[w][c*16 + k];
        float part = wx[c*13 + 10] * xin[n*2 + c]
                   + wx[c*13 + 11] * wc0 * xsc[w][c*16 + n]
                   + wx[c*13 + 12] * wc0 * g;
        xsc[w][32 + lane] = part;
    }
    __syncwarp();
    if (lane < 16) {
        float xg = xsc[w][32 + lane] + xsc[w][48 + lane] + gcn_bx[t*16 + lane];
        xsc[w][64 + lane] = fmaxf(xg, 0.0f);
    }
    __syncwarp();

    // ---- u vectors ----
    const float* gk = gru_k + (size_t)t * 1536;
    const float* gb = gru_b + t * 96;
    for (int e = lane; e < 48; e += 32) {
        int i2 = e >> 4, j = e & 15;
        const float* Kb = gk + i2 * 512;
        float u = gb[i2*32 + j] + gb[i2*32 + 16 + j];
        #pragma unroll
        for (int m = 0; m < 16; m++) u += xsc[w][64 + m] * Kb[m*16 + j];
        if (i2 == 0)      bs[w][BIDX(j, 32)] = u;
        else if (i2 == 1) bs[w][BIDX(16 + j, 32)] = u;
        else { bs[w][BIDX(j, 34)] = 0.5f*u; bs[w][BIDX(16 + j, 34)] = 0.5f*u; }
    }

    // ---- K1/K3/K5 columns (R6 layout) ----
    for (int e = lane; e < 768; e += 32) {
        int which = e >> 8, rc = e & 255, m = rc >> 4, nn = rc & 15;
        float kv = gk[(2*which + 1)*256 + m*16 + nn];
        int ln, f;
        if (which == 0)      { ln = nn;                        f = 8 + m; }
        else if (which == 1) { ln = 16 + nn;                   f = 8 + m; }
        else                 { ln = (m < 8) ? nn : 16 + nn;    f = 24 + (m & 7); }
        bs[w][BIDX(ln, f)] = kv;
    }

    // ---- bh/2 (both halves) ----
    if (lane < 16) {
        float bh = (t == 0) ? 0.0f : gcn_bh[t*16 + lane];
        bs[w][BIDX(lane, 33)] = 0.5f*bh;
        bs[w][BIDX(16 + lane, 33)] = 0.5f*bh;
    }
    __syncwarp();

    float4* dst = reinterpret_cast<float4*>(g_blob + (size_t)t * 1152);
    const float4* srcv = reinterpret_cast<const float4*>(bs[w]);
    for (int i = lane; i < 288; i += 32) dst[i] = srcv[i];
}

// ---------------------------------------------------------------------------
// Recurrence kernel
// ---------------------------------------------------------------------------
__device__ __forceinline__ int ldacq(uint32_t a){
    int v; asm volatile("ld.acquire.cta.shared::cta.b32 %0, [%1];" : "=r"(v) : "r"(a)); return v;
}

// Predicated global store: no BSSY/BSYNC.
__device__ __forceinline__ void st_pred(float* p, float v, uint32_t pred){
    asm volatile("{\n\t.reg .pred q;\n\t.reg .f32 dummy;\n\tsetp.ne.u32 q, %2, 0;\n\t@q st.global.f32 [%0], %1;\n\t}"
                 :: "l"(p), "f"(v), "r"(pred) : "memory");
}

__device__ __forceinline__ void gru_step(const float (&w)[36], float (&hv)[8],
                                         float* __restrict__ out, int t,
                                         uint32_t hip, int rsrc, int hsrc,
                                         uint32_t hgb, uint32_t hgslot)
{
    // hg = relu(A@h + bh), split across halves; bh/2 folded into each half
    float a0 = fmaf(w[0], hv[0], w[33]);
    float a1 = w[1]*hv[1];
    a0 = fmaf(w[2], hv[2], a0); a1 = fmaf(w[3], hv[3], a1);
    a0 = fmaf(w[4], hv[4], a0); a1 = fmaf(w[5], hv[5], a1);
    a0 = fmaf(w[6], hv[6], a0); a1 = fmaf(w[7], hv[7], a1);
    float pa = a0 + a1;
    pa += __shfl_xor_sync(FULLMASK, pa, 16);
    float hg = fmaxf(pa, 0.0f);

    // hg exchange via smem: 1 STS + 4 LDS.128 (replaces 16 SHFLs).
    // Lanes n and n+16 store the same value to the same address (benign).
    // Converged warp executes smem ops in order; volatile pins compiler order.
    float hgv[16];
    asm volatile("st.volatile.shared.f32 [%0], %1;" :: "r"(hgslot), "f"(hg));
    asm volatile("ld.volatile.shared.v4.f32 {%0,%1,%2,%3}, [%4];"
                 : "=f"(hgv[0]),"=f"(hgv[1]),"=f"(hgv[2]),"=f"(hgv[3]) : "r"(hgb));
    asm volatile("ld.volatile.shared.v4.f32 {%0,%1,%2,%3}, [%4];"
                 : "=f"(hgv[4]),"=f"(hgv[5]),"=f"(hgv[6]),"=f"(hgv[7]) : "r"(hgb + 16));
    asm volatile("ld.volatile.shared.v4.f32 {%0,%1,%2,%3}, [%4];"
                 : "=f"(hgv[8]),"=f"(hgv[9]),"=f"(hgv[10]),"=f"(hgv[11]) : "r"(hgb + 32));
    asm volatile("ld.volatile.shared.v4.f32 {%0,%1,%2,%3}, [%4];"
                 : "=f"(hgv[12]),"=f"(hgv[13]),"=f"(hgv[14]),"=f"(hgv[15]) : "r"(hgb + 48));

    // r (lo) / z (hi) dot
    float v0 = w[32], v1 = 0.0f;
    #pragma unroll
    for (int m = 0; m < 16; m += 2) {
        v0 = fmaf(hgv[m],   w[8 + m], v0);
        v1 = fmaf(hgv[m+1], w[9 + m], v1);
    }
    float s = sigm(v0 + v1);
    float rh = s * hg;     // meaningful in lo lanes (r*hg)

    // broadcast rh (own m-half: 8 values from lo lanes)
    float rhv[8];
    #pragma unroll
    for (int j = 0; j < 8; j++) rhv[j] = __shfl_sync(FULLMASK, rh, rsrc + j);

    // hc partial, split across halves; u4/2 folded into each half
    float p0 = fmaf(rhv[0], w[24], w[34]);
    float p1 = rhv[1]*w[25];
    p0 = fmaf(rhv[2], w[26], p0); p1 = fmaf(rhv[3], w[27], p1);
    p0 = fmaf(rhv[4], w[28], p0); p1 = fmaf(rhv[5], w[29], p1);
    p0 = fmaf(rhv[6], w[30], p0); p1 = fmaf(rhv[7], w[31], p1);
    float p = p0 + p1;
    p += __shfl_xor_sync(FULLMASK, p, 16);
    float hc = tanha(p);
    float hn = fmaf(s, hg - hc, hc);      // meaningful in hi lanes (s = z)

    // broadcast next h (own m-half, sourced from hi lanes)
    #pragma unroll
    for (int j = 0; j < 8; j++) hv[j] = __shfl_sync(FULLMASK, hn, hsrc + j);

    // predicated store, off the critical chain
    st_pred(out + t * 16 + (threadIdx.x & 15), hn, hip);
}

#define LOADW(dst, slot)                                                     \
    {                                                                        \
        const float4* _s = &ring[(slot) * 288 + lane];                       \
        float4* _d = reinterpret_cast<float4*>(dst);                         \
        _Pragma("unroll")                                                    \
        for (int _j = 0; _j < 9; _j++) _d[_j] = _s[_j * 32];                 \
    }

__global__ void __launch_bounds__(128) recurrent_kernel(float* __restrict__ out)
{
    __shared__ float4 ring[RING * 288];
    __shared__ float hgbuf[16];
    __shared__ int Wsh;
    __shared__ int cons_prog;

    int tid = threadIdx.x;
    if (tid == 0) { Wsh = 0; cons_prog = 0; }
    __syncthreads();

    int w = tid >> 5, lane = tid & 31;

    if (w == 0) {
        // ---------------- consumer ----------------
        uint32_t hip = (lane >= 16) ? 1u : 0u;
        int rsrc = (lane >= 16) ? 8 : 0;
        int hsrc = (lane >= 16) ? 24 : 16;
        uint32_t hgb = (uint32_t)__cvta_generic_to_shared(hgbuf);
        uint32_t hgslot = hgb + ((uint32_t)(lane & 15) << 2);

        float hv[8];
        #pragma unroll
        for (int j = 0; j < 8; j++) hv[j] = 0.0f;

        uint32_t Wa = (uint32_t)__cvta_generic_to_shared(&Wsh);
        int Wloc = 0;

        float wa[36], wb[36];
        while (Wloc < 1) Wloc = ldacq(Wa);
        LOADW(wa, 0);

        #pragma unroll 1
        for (int t = 0; t < T_STEPS; t += 2) {
            // poll for t+1 data (R6 placement: demand no earlier than needed)
            while (Wloc < t + 2) Wloc = ldacq(Wa);
            LOADW(wb, (t + 1) & (RING - 1));

            gru_step(wa, hv, out, t, hip, rsrc, hsrc, hgb, hgslot);

            // poll for t+2 data at the midpoint (after step t's compute)
            if (t + 2 < T_STEPS) {
                while (Wloc < t + 3) Wloc = ldacq(Wa);
                LOADW(wa, (t + 2) & (RING - 1));
            }

            gru_step(wb, hv, out, t + 1, hip, rsrc, hsrc, hgb, hgslot);

            // all lanes store same value to same address: no divergence
            *(volatile int*)&cons_prog = t + 2;
        }
    } else if (w == 1) {
        // ---------------- producer (single warp, monotonic watermark) ----
        // wait_group 2 lag: publish t-1 after commit t. Slack vs consumer = 3.
        uint32_t ringb = (uint32_t)__cvta_generic_to_shared(ring);
        uint32_t Wa = (uint32_t)__cvta_generic_to_shared(&Wsh);
        const float4* blob4 = reinterpret_cast<const float4*>(g_blob);

        for (int t = 0; t < T_STEPS; t++) {
            if (t >= RING) {
                while (*(volatile int*)&cons_prog < t - RING + 1) __nanosleep(32);
            }
            const float4* src = blob4 + (size_t)t * 288 + lane;
            uint32_t dst = ringb + ((uint32_t)(t & (RING - 1)) * 288 + lane) * 16;
            #pragma unroll
            for (int j = 0; j < 9; j++) {
                asm volatile("cp.async.cg.shared.global [%0], [%1], 16;"
                             :: "r"(dst + j * 512), "l"(src + j * 32) : "memory");
            }
            asm volatile("cp.async.commit_group;" ::: "memory");
            asm volatile("cp.async.wait_group 2;" ::: "memory");
            __threadfence_block();
            __syncwarp();
            if (lane == 0 && t >= 2) {
                asm volatile("st.release.cta.shared::cta.b32 [%0], %1;"
                             :: "r"(Wa), "r"(t - 1) : "memory");
            }
        }
        asm volatile("cp.async.wait_group 0;" ::: "memory");
        __threadfence_block();
        __syncwarp();
        if (lane == 0) {
            asm volatile("st.release.cta.shared::cta.b32 [%0], %1;"
                         :: "r"(Wa), "r"(T_STEPS + RING) : "memory");
        }
    } else if (w == 2) {
        // ---------------- L2 prefetcher ----------------
        const char* p = reinterpret_cast<const char*>(g_blob);
        size_t total = (size_t)T_STEPS * 4608;
        #pragma unroll 4
        for (size_t off = (size_t)lane * 128; off < total; off += 4096) {
            asm volatile("prefetch.global.L2 [%0];" :: "l"(p + off));
        }
    }
}

extern "C" void kernel_launch(void* const* d_in, const int* in_sizes, int n_in,
                              void* d_out, int out_size)
{
    const float* inputs = (const float*)d_in[0];
    const float* a_list = (const float*)d_in[1];
    const float* gcn_wx = (const float*)d_in[2];
    const float* gcn_bx = (const float*)d_in[3];
    const float* gcn_wh = (const float*)d_in[4];
    const float* gcn_bh = (const float*)d_in[5];
    const float* gru_k  = (const float*)d_in[6];
    const float* gru_b  = (const float*)d_in[7];

    precompute_kernel<<<4096, 128>>>(inputs, a_list, gcn_wx, gcn_bx,
                                     gcn_wh, gcn_bh, gru_k, gru_b);
    recurrent_kernel<<<1, 128>>>((float*)d_out);
}

// round 10
// speedup vs baseline: 1.4005x; 1.1269x over previous
#include <cuda_runtime.h>
#include <cstdint>

#define T_STEPS 16384
#define RING 8
#define FULLMASK 0xffffffffu

// Per-step blob, 36 floats per lane (32 lanes) = 1152 floats = 4608 B/step.
// Lane L (n = L&15, hi = L>=16):
//  f[0..7]   : A[n][m] for m in lo?0..7:8..15      (hg partial)
//  f[8..23]  : K1 col n (lo) / K3 col n (hi)       (r/z dot)
//  f[24..31] : K5[m][n], m in lo?0..7:8..15        (hc partial)
//  f[32]     : u0[n] (lo) / u2[n] (hi)
//  f[33]     : bh[n]/2  (both halves; halves sum across the xor)
//  f[34]     : u4[n]/2  (both halves)
//  f[35]     : pad
// Storage: blob[t][g][L] as float4, g = f>>2 (0..8), L = 0..31.
__device__ float g_blob[(size_t)T_STEPS * 1152];

#define BIDX(ln, f) ((((f) >> 2) * 128) + ((ln) * 4) + ((f) & 3))

__device__ __forceinline__ float tanha(float x){
    float y; asm("tanh.approx.f32 %0, %1;" : "=f"(y) : "f"(x)); return y;
}
__device__ __forceinline__ float sigm(float x){ return fmaf(0.5f, tanha(0.5f * x), 0.5f); }

// ---------------------------------------------------------------------------
// Precompute kernel: one warp per timestep.
// ---------------------------------------------------------------------------
__global__ void __launch_bounds__(128) precompute_kernel(
    const float* __restrict__ inputs, const float* __restrict__ a_list,
    const float* __restrict__ gcn_wx, const float* __restrict__ gcn_bx,
    const float* __restrict__ gcn_wh, const float* __restrict__ gcn_bh,
    const float* __restrict__ gru_k,  const float* __restrict__ gru_b)
{
    __shared__ float Lh[3][16][16];
    __shared__ float Lsum[16][16];
    __shared__ float dd[3][16], dis[3][16];
    __shared__ float Qh[4][256];
    __shared__ float bs[4][1152];
    __shared__ float xsc[4][80];

    int tid = threadIdx.x;

    if (tid < 48) {
        int l = tid / 16, j = tid % 16;
        float s = 0.0f;
        #pragma unroll
        for (int i = 0; i < 16; i++) s += a_list[l*256 + i*16 + j];
        dd[l][j] = s;
        dis[l][j] = rsqrtf(s);
    }
    __syncthreads();
    for (int e = tid; e < 768; e += 128) {
        int l = e / 256, rc = e % 256, i = rc / 16, j = rc % 16;
        float Lv = ((i == j) ? dd[l][i] : 0.0f) - a_list[e];
        Lh[l][i][j] = Lv * dis[l][i] * dis[l][j];
    }
    __syncthreads();
    {
        float* LsF = &Lsum[0][0];
        float* LhF = &Lh[0][0][0];
        for (int e = tid; e < 256; e += 128)
            LsF[e] = LhF[e] + LhF[256 + e] + LhF[512 + e];
    }
    __syncthreads();

    int w = tid >> 5, lane = tid & 31;
    int t = blockIdx.x * 4 + w;

    float* LsF = &Lsum[0][0];
    float* LhF = &Lh[0][0][0];

    // zero staging
    for (int i = lane; i < 1152; i += 32) bs[w][i] = 0.0f;
    __syncwarp();

    // ---- h-GCN matrix A ----
    const float* wh = gcn_wh + t * 13;
    float wh0 = wh[0], wh1 = wh[1], wh2 = wh[2];
    float wh10 = wh[10], wh11 = wh[11], wh12 = wh[12];

    for (int e = lane; e < 256; e += 32)
        Qh[w][e] = wh0*LhF[e] + wh1*LhF[256+e] + wh2*LhF[512+e];
    __syncwarp();

    float cA1 = wh0 * wh11, cA2 = wh0 * wh12;
    for (int e = lane; e < 256; e += 32) {
        int n = e >> 4, m = e & 15;
        float ql = 0.0f;
        #pragma unroll
        for (int k = 0; k < 16; k++) ql += Qh[w][n*16 + k] * LsF[k*16 + m];
        float Av = ((n == m) ? wh10 : 0.0f) + cA1 * LsF[e] + cA2 * ql;
        if (t == 0) Av = 0.0f;
        int ln = (m < 8) ? n : 16 + n;
        bs[w][BIDX(ln, m & 7)] = Av;
    }

    // ---- x-GCN -> xg ----
    const float* wx  = gcn_wx + t * 26;
    const float* xin = inputs + t * 32;
    {
        int c = lane >> 4, k = lane & 15;
        float s = 0.0f;
        #pragma unroll
        for (int m = 0; m < 16; m++) s += LsF[k*16 + m] * xin[m*2 + c];
        xsc[w][lane] = s;
    }
    __syncwarp();
    {
        int c = lane >> 4, n = lane & 15;
        float wc0 = wx[c*13], wc1 = wx[c*13 + 1], wc2 = wx[c*13 + 2];
        float g = 0.0f;
        #pragma unroll
        for (int k = 0; k < 16; k++)
            g += (wc0*Lh[0][n][k] + wc1*Lh[1][n][k] + wc2*Lh[2][n][k]) * xsc[w][c*16 + k];
        float part = wx[c*13 + 10] * xin[n*2 + c]
                   + wx[c*13 + 11] * wc0 * xsc[w][c*16 + n]
                   + wx[c*13 + 12] * wc0 * g;
        xsc[w][32 + lane] = part;
    }
    __syncwarp();
    if (lane < 16) {
        float xg = xsc[w][32 + lane] + xsc[w][48 + lane] + gcn_bx[t*16 + lane];
        xsc[w][64 + lane] = fmaxf(xg, 0.0f);
    }
    __syncwarp();

    // ---- u vectors ----
    const float* gk = gru_k + (size_t)t * 1536;
    const float* gb = gru_b + t * 96;
    for (int e = lane; e < 48; e += 32) {
        int i2 = e >> 4, j = e & 15;
        const float* Kb = gk + i2 * 512;
        float u = gb[i2*32 + j] + gb[i2*32 + 16 + j];
        #pragma unroll
        for (int m = 0; m < 16; m++) u += xsc[w][64 + m] * Kb[m*16 + j];
        if (i2 == 0)      bs[w][BIDX(j, 32)] = u;
        else if (i2 == 1) bs[w][BIDX(16 + j, 32)] = u;
        else { bs[w][BIDX(j, 34)] = 0.5f*u; bs[w][BIDX(16 + j, 34)] = 0.5f*u; }
    }

    // ---- K1/K3/K5 columns (R6 layout) ----
    for (int e = lane; e < 768; e += 32) {
        int which = e >> 8, rc = e & 255, m = rc >> 4, nn = rc & 15;
        float kv = gk[(2*which + 1)*256 + m*16 + nn];
        int ln, f;
        if (which == 0)      { ln = nn;                        f = 8 + m; }
        else if (which == 1) { ln = 16 + nn;                   f = 8 + m; }
        else                 { ln = (m < 8) ? nn : 16 + nn;    f = 24 + (m & 7); }
        bs[w][BIDX(ln, f)] = kv;
    }

    // ---- bh/2 (both halves) ----
    if (lane < 16) {
        float bh = (t == 0) ? 0.0f : gcn_bh[t*16 + lane];
        bs[w][BIDX(lane, 33)] = 0.5f*bh;
        bs[w][BIDX(16 + lane, 33)] = 0.5f*bh;
    }
    __syncwarp();

    float4* dst = reinterpret_cast<float4*>(g_blob + (size_t)t * 1152);
    const float4* srcv = reinterpret_cast<const float4*>(bs[w]);
    for (int i = lane; i < 288; i += 32) dst[i] = srcv[i];
}

// ---------------------------------------------------------------------------
// Recurrence kernel
// ---------------------------------------------------------------------------
__device__ __forceinline__ int ldacq(uint32_t a){
    int v; asm volatile("ld.acquire.cta.shared::cta.b32 %0, [%1];" : "=r"(v) : "r"(a)); return v;
}

// Predicated global store: no BSSY/BSYNC.
__device__ __forceinline__ void st_pred(float* p, float v, uint32_t pred){
    asm volatile("{\n\t.reg .pred q;\n\tsetp.ne.u32 q, %2, 0;\n\t@q st.global.f32 [%0], %1;\n\t}"
                 :: "l"(p), "f"(v), "r"(pred) : "memory");
}

__device__ __forceinline__ void sts_f32(uint32_t a, float v){
    asm volatile("st.volatile.shared.f32 [%0], %1;" :: "r"(a), "f"(v));
}
__device__ __forceinline__ void lds_v4(float* d, uint32_t a){
    asm volatile("ld.volatile.shared.v4.f32 {%0,%1,%2,%3}, [%4];"
                 : "=f"(d[0]),"=f"(d[1]),"=f"(d[2]),"=f"(d[3]) : "r"(a));
}

// All inter-lane broadcasts via smem (converged warp => in-order LSU; volatile
// pins compiler order). Only the two 1-value cross-half hops stay as shfl_xor.
__device__ __forceinline__ void gru_step(const float (&w)[36], float (&hv)[8],
                                         float* __restrict__ out, int t,
                                         uint32_t hip,
                                         uint32_t hgb, uint32_t hgslot,
                                         uint32_t rhslot, uint32_t rhread,
                                         uint32_t hslot,  uint32_t hread)
{
    // hg = relu(A@h + bh), split across halves; bh/2 folded into each half
    float a0 = fmaf(w[0], hv[0], w[33]);
    float a1 = w[1]*hv[1];
    a0 = fmaf(w[2], hv[2], a0); a1 = fmaf(w[3], hv[3], a1);
    a0 = fmaf(w[4], hv[4], a0); a1 = fmaf(w[5], hv[5], a1);
    a0 = fmaf(w[6], hv[6], a0); a1 = fmaf(w[7], hv[7], a1);
    float pa = a0 + a1;
    pa += __shfl_xor_sync(FULLMASK, pa, 16);
    float hg = fmaxf(pa, 0.0f);

    // hg exchange: 1 STS + 4 LDS.128 (lanes n and n+16 write same value: benign)
    float hgv[16];
    sts_f32(hgslot, hg);
    lds_v4(hgv + 0,  hgb);
    lds_v4(hgv + 4,  hgb + 16);
    lds_v4(hgv + 8,  hgb + 32);
    lds_v4(hgv + 12, hgb + 48);

    // r (lo) / z (hi) dot
    float v0 = w[32], v1 = 0.0f;
    #pragma unroll
    for (int m = 0; m < 16; m += 2) {
        v0 = fmaf(hgv[m],   w[8 + m], v0);
        v1 = fmaf(hgv[m+1], w[9 + m], v1);
    }
    float s = sigm(v0 + v1);
    float rh = s * hg;     // meaningful in lo lanes (r*hg)

    // rh exchange: STS to per-lane slot; lo lanes read rhbuf[0..7], hi [8..15]
    float rhv[8];
    sts_f32(rhslot, rh);
    lds_v4(rhv + 0, rhread);
    lds_v4(rhv + 4, rhread + 16);

    // hc partial, split across halves; u4/2 folded into each half
    float p0 = fmaf(rhv[0], w[24], w[34]);
    float p1 = rhv[1]*w[25];
    p0 = fmaf(rhv[2], w[26], p0); p1 = fmaf(rhv[3], w[27], p1);
    p0 = fmaf(rhv[4], w[28], p0); p1 = fmaf(rhv[5], w[29], p1);
    p0 = fmaf(rhv[6], w[30], p0); p1 = fmaf(rhv[7], w[31], p1);
    float p = p0 + p1;
    p += __shfl_xor_sync(FULLMASK, p, 16);
    float hc = tanha(p);
    float hn = fmaf(s, hg - hc, hc);      // meaningful in hi lanes (s = z)

    // h exchange: STS to per-lane slot; read own m-half from hi-lane copies
    sts_f32(hslot, hn);
    lds_v4(hv + 0, hread);
    lds_v4(hv + 4, hread + 16);

    // predicated store, off the critical chain
    st_pred(out + t * 16 + (threadIdx.x & 15), hn, hip);
}

#define LOADW(dst, slot)                                                     \
    {                                                                        \
        const float4* _s = &ring[(slot) * 288 + lane];                       \
        float4* _d = reinterpret_cast<float4*>(dst);                         \
        _Pragma("unroll")                                                    \
        for (int _j = 0; _j < 9; _j++) _d[_j] = _s[_j * 32];                 \
    }

__global__ void __launch_bounds__(128) recurrent_kernel(float* __restrict__ out)
{
    __shared__ float4 ring[RING * 288];
    __shared__ __align__(16) float hgbuf[16];
    __shared__ __align__(16) float rhbuf[32];
    __shared__ __align__(16) float hbuf[32];
    __shared__ int Wsh;
    __shared__ int cons_prog;

    int tid = threadIdx.x;
    if (tid == 0) { Wsh = 0; cons_prog = 0; }
    __syncthreads();

    int w = tid >> 5, lane = tid & 31;

    if (w == 0) {
        // ---------------- consumer ----------------
        uint32_t hip = (lane >= 16) ? 1u : 0u;
        uint32_t hgb = (uint32_t)__cvta_generic_to_shared(hgbuf);
        uint32_t hgslot = hgb + ((uint32_t)(lane & 15) << 2);
        uint32_t rhb = (uint32_t)__cvta_generic_to_shared(rhbuf);
        uint32_t rhslot = rhb + ((uint32_t)lane << 2);
        uint32_t rhread = rhb + (hip ? 32u : 0u);      // rhbuf[8..15] : [0..7]
        uint32_t hb  = (uint32_t)__cvta_generic_to_shared(hbuf);
        uint32_t hslot = hb + ((uint32_t)lane << 2);
        uint32_t hread = hb + (hip ? 96u : 64u);       // hbuf[24..31] : [16..23]

        float hv[8];
        #pragma unroll
        for (int j = 0; j < 8; j++) hv[j] = 0.0f;

        uint32_t Wa = (uint32_t)__cvta_generic_to_shared(&Wsh);
        int Wloc = 0;

        float wa[36], wb[36];
        while (Wloc < 1) Wloc = ldacq(Wa);
        LOADW(wa, 0);

        #pragma unroll 1
        for (int t = 0; t < T_STEPS; t += 2) {
            // poll for t+1 data (demand no earlier than needed)
            while (Wloc < t + 2) Wloc = ldacq(Wa);
            LOADW(wb, (t + 1) & (RING - 1));

            gru_step(wa, hv, out, t, hip, hgb, hgslot, rhslot, rhread, hslot, hread);

            // poll for t+2 data at the midpoint (after step t's compute)
            if (t + 2 < T_STEPS) {
                while (Wloc < t + 3) Wloc = ldacq(Wa);
                LOADW(wa, (t + 2) & (RING - 1));
            }

            gru_step(wb, hv, out, t + 1, hip, hgb, hgslot, rhslot, rhread, hslot, hread);

            // all lanes store same value to same address: no divergence
            *(volatile int*)&cons_prog = t + 2;
        }
    } else if (w == 1) {
        // ---------------- producer (single warp, monotonic watermark) ----
        // wait_group 2 lag: publish t-1 after commit t. Slack vs consumer = 3.
        uint32_t ringb = (uint32_t)__cvta_generic_to_shared(ring);
        uint32_t Wa = (uint32_t)__cvta_generic_to_shared(&Wsh);
        const float4* blob4 = reinterpret_cast<const float4*>(g_blob);

        for (int t = 0; t < T_STEPS; t++) {
            if (t >= RING) {
                while (*(volatile int*)&cons_prog < t - RING + 1) __nanosleep(32);
            }
            const float4* src = blob4 + (size_t)t * 288 + lane;
            uint32_t dst = ringb + ((uint32_t)(t & (RING - 1)) * 288 + lane) * 16;
            #pragma unroll
            for (int j = 0; j < 9; j++) {
                asm volatile("cp.async.cg.shared.global [%0], [%1], 16;"
                             :: "r"(dst + j * 512), "l"(src + j * 32) : "memory");
            }
            asm volatile("cp.async.commit_group;" ::: "memory");
            asm volatile("cp.async.wait_group 2;" ::: "memory");
            __threadfence_block();
            __syncwarp();
            if (lane == 0 && t >= 2) {
                asm volatile("st.release.cta.shared::cta.b32 [%0], %1;"
                             :: "r"(Wa), "r"(t - 1) : "memory");
            }
        }
        asm volatile("cp.async.wait_group 0;" ::: "memory");
        __threadfence_block();
        __syncwarp();
        if (lane == 0) {
            asm volatile("st.release.cta.shared::cta.b32 [%0], %1;"
                         :: "r"(Wa), "r"(T_STEPS + RING) : "memory");
        }
    } else if (w == 2) {
        // ---------------- L2 prefetcher ----------------
        const char* p = reinterpret_cast<const char*>(g_blob);
        size_t total = (size_t)T_STEPS * 4608;
        #pragma unroll 4
        for (size_t off = (size_t)lane * 128; off < total; off += 4096) {
            asm volatile("prefetch.global.L2 [%0];" :: "l"(p + off));
        }
    }
}

extern "C" void kernel_launch(void* const* d_in, const int* in_sizes, int n_in,
                              void* d_out, int out_size)
{
    const float* inputs = (const float*)d_in[0];
    const float* a_list = (const float*)d_in[1];
    const float* gcn_wx = (const float*)d_in[2];
    const float* gcn_bx = (const float*)d_in[3];
    const float* gcn_wh = (const float*)d_in[4];
    const float* gcn_bh = (const float*)d_in[5];
    const float* gru_k  = (const float*)d_in[6];
    const float* gru_b  = (const float*)d_in[7];

    precompute_kernel<<<4096, 128>>>(inputs, a_list, gcn_wx, gcn_bx,
                                     gcn_wh, gcn_bh, gru_k, gru_b);
    recurrent_kernel<<<1, 128>>>((float*)d_out);
}